// round 1
// baseline (speedup 1.0000x reference)
#include <cuda_runtime.h>
#include <math.h>

// Problem constants
#define BDIM 4
#define TDIM 4096
#define CDIM 1024
#define HDIM 2048
#define MTOT (BDIM * TDIM)   // 16384

// Scratch (device globals: allocation-free per harness rules)
__device__ float g_s[(size_t)MTOT * HDIM];       // s, later s*agg   (128 MB)
__device__ float g_h[(size_t)MTOT * 2 * HDIM];   // h = x@W_agg*sqk  (256 MB)

// ---------------------------------------------------------------------------
// Tiled fp32 GEMM: C[M,N] = A[M,K] @ W[K,N], row-major everywhere.
// 128x128 block tile, BK=16, 256 threads, 8x8 per thread, smem double buffer.
// EPI: 0 = y*scale[n] ; 1 = silu(y*scale[n]) ; 2 = plain
// ---------------------------------------------------------------------------
constexpr int BM = 128, BN = 128, BK = 16;
constexpr int APAD = 4;  // pad transposed A-tile rows to soften store conflicts

template <int EPI>
__global__ __launch_bounds__(256)
void sgemm(const float* __restrict__ A, const float* __restrict__ W,
           float* __restrict__ Cout, const float* __restrict__ scale,
           int M, int N, int K)
{
    __shared__ float As[2][BK][BM + APAD];
    __shared__ float Bs[2][BK][BN];

    const int tid = threadIdx.x;
    const int bn = blockIdx.x * BN;
    const int bm = blockIdx.y * BM;
    const int tx = tid & 15;        // 0..15  -> n sub-tile
    const int ty = tid >> 4;        // 0..15  -> m sub-tile

    // Global load mapping: 512 float4 for A-tile (128x16), 512 for B-tile (16x128)
    const int arow0 = tid >> 2;          // 0..63 (second load +64)
    const int acol  = (tid & 3) * 4;     // 0,4,8,12
    const int brow0 = tid >> 5;          // 0..7  (second load +8)
    const int bcol  = (tid & 31) * 4;    // 0..124

    const float* Aptr = A + (size_t)bm * K;
    const float* Wptr = W + bn;

    float4 aReg[2], bReg[2];

    // Prologue: load k-tile 0
#pragma unroll
    for (int i = 0; i < 2; i++) {
        int ar = arow0 + i * 64;
        aReg[i] = *(const float4*)(Aptr + (size_t)ar * K + acol);
        int br = brow0 + i * 8;
        bReg[i] = *(const float4*)(Wptr + (size_t)br * N + bcol);
    }
#pragma unroll
    for (int i = 0; i < 2; i++) {
        int ar = arow0 + i * 64;
        As[0][acol + 0][ar] = aReg[i].x;
        As[0][acol + 1][ar] = aReg[i].y;
        As[0][acol + 2][ar] = aReg[i].z;
        As[0][acol + 3][ar] = aReg[i].w;
        int br = brow0 + i * 8;
        *(float4*)(&Bs[0][br][bcol]) = bReg[i];
    }
    __syncthreads();

    float acc[8][8] = {};

    const int ntiles = K / BK;
    for (int t = 0; t < ntiles; ++t) {
        const int buf = t & 1;
        // Prefetch next k-tile from global into registers
        if (t + 1 < ntiles) {
            const int k0 = (t + 1) * BK;
#pragma unroll
            for (int i = 0; i < 2; i++) {
                int ar = arow0 + i * 64;
                aReg[i] = *(const float4*)(Aptr + (size_t)ar * K + k0 + acol);
                int br = brow0 + i * 8;
                bReg[i] = *(const float4*)(Wptr + (size_t)(k0 + br) * N + bcol);
            }
        }
        // Compute on current buffer
#pragma unroll
        for (int kk = 0; kk < BK; ++kk) {
            float4 a0 = *(const float4*)(&As[buf][kk][ty * 8]);
            float4 a1 = *(const float4*)(&As[buf][kk][ty * 8 + 4]);
            float4 b0 = *(const float4*)(&Bs[buf][kk][tx * 8]);
            float4 b1 = *(const float4*)(&Bs[buf][kk][tx * 8 + 4]);
            float av[8] = {a0.x, a0.y, a0.z, a0.w, a1.x, a1.y, a1.z, a1.w};
            float bv[8] = {b0.x, b0.y, b0.z, b0.w, b1.x, b1.y, b1.z, b1.w};
#pragma unroll
            for (int i = 0; i < 8; i++)
#pragma unroll
                for (int j = 0; j < 8; j++)
                    acc[i][j] = fmaf(av[i], bv[j], acc[i][j]);
        }
        // Stage next tile into the other buffer
        if (t + 1 < ntiles) {
            const int nb = buf ^ 1;
#pragma unroll
            for (int i = 0; i < 2; i++) {
                int ar = arow0 + i * 64;
                As[nb][acol + 0][ar] = aReg[i].x;
                As[nb][acol + 1][ar] = aReg[i].y;
                As[nb][acol + 2][ar] = aReg[i].z;
                As[nb][acol + 3][ar] = aReg[i].w;
                int br = brow0 + i * 8;
                *(float4*)(&Bs[nb][br][bcol]) = bReg[i];
            }
            __syncthreads();
        }
    }

    // Epilogue
    float sc[8];
    if (EPI == 0 || EPI == 1) {
#pragma unroll
        for (int j = 0; j < 8; j++) sc[j] = scale[bn + tx * 8 + j];
    }
#pragma unroll
    for (int i = 0; i < 8; i++) {
        int m = bm + ty * 8 + i;
        float* crow = Cout + (size_t)m * N + bn + tx * 8;
#pragma unroll
        for (int j = 0; j < 8; j += 4) {
            float vv[4];
#pragma unroll
            for (int q = 0; q < 4; q++) {
                float y = acc[i][j + q];
                if (EPI == 0 || EPI == 1) y *= sc[j + q];
                if (EPI == 1) y = y / (1.0f + expf(-y));  // silu
                vv[q] = y;
            }
            *(float4*)(crow + j) = make_float4(vv[0], vv[1], vv[2], vv[3]);
        }
    }
}

// ---------------------------------------------------------------------------
// Fused polynomial + causal running mean + gate:
//   poly[t] = c0 + c0*c1,  acc = cumsum_t(poly),  s[t] *= acc/(t+1)
// One thread per (batch, channel); loads coalesced across channels.
// ---------------------------------------------------------------------------
__global__ void cumsum_fuse(const float* __restrict__ h, float* __restrict__ s)
{
    const int ch = blockIdx.x * blockDim.x + threadIdx.x;  // 0..HDIM-1
    const int b  = blockIdx.y;
    const float* hp = h + (size_t)b * TDIM * (2 * HDIM) + ch;
    float* sp = s + (size_t)b * TDIM * HDIM + ch;

    float acc = 0.0f;
#pragma unroll 4
    for (int t = 0; t < TDIM; ++t) {
        float c0 = hp[(size_t)t * (2 * HDIM)];
        float c1 = hp[(size_t)t * (2 * HDIM) + HDIM];
        acc += fmaf(c0, c1, c0);            // acc += c0 + c0*c1
        float val = acc / (float)(t + 1);   // causal running mean
        size_t off = (size_t)t * HDIM;
        sp[off] = sp[off] * val;            // gate: s * agg (in place)
    }
}

// ---------------------------------------------------------------------------
// Launch
// ---------------------------------------------------------------------------
extern "C" void kernel_launch(void* const* d_in, const int* in_sizes, int n_in,
                              void* d_out, int out_size)
{
    const float* x     = (const float*)d_in[0];
    const float* W_sel = (const float*)d_in[1];
    const float* W_agg = (const float*)d_in[2];
    const float* W_out = (const float*)d_in[3];
    const float* sqk_q = (const float*)d_in[4];
    const float* sqk_k = (const float*)d_in[5];
    float* out = (float*)d_out;

    float *s_ptr, *h_ptr;
    cudaGetSymbolAddress((void**)&s_ptr, g_s);
    cudaGetSymbolAddress((void**)&h_ptr, g_h);

    dim3 blk(256);
    // s = silu((x @ W_sel) * sqk_q)            [16384 x 2048, K=1024]
    sgemm<1><<<dim3(HDIM / BN, MTOT / BM), blk>>>(x, W_sel, s_ptr, sqk_q,
                                                  MTOT, HDIM, CDIM);
    // h = (x @ W_agg) * sqk_k                  [16384 x 4096, K=1024]
    sgemm<0><<<dim3(2 * HDIM / BN, MTOT / BM), blk>>>(x, W_agg, h_ptr, sqk_k,
                                                      MTOT, 2 * HDIM, CDIM);
    // poly -> causal running mean -> s *= agg  (in place on g_s)
    cumsum_fuse<<<dim3(HDIM / 64, BDIM), 64>>>(h_ptr, s_ptr);
    // out = (s*agg) @ W_out                    [16384 x 1024, K=2048]
    sgemm<2><<<dim3(CDIM / BN, MTOT / BM), blk>>>(s_ptr, W_out, out, nullptr,
                                                  MTOT, CDIM, HDIM);
}